// round 2
// baseline (speedup 1.0000x reference)
#include <cuda_runtime.h>
#include <cstddef>

#define TSTEPS 1024
#define BATCH  128
#define DIN    64
#define HH     512
#define NTHR   512
#define EPSF   1e-5f

__device__ __forceinline__ void fma4(float4& a, float h, const float4 w) {
    a.x = fmaf(h, w.x, a.x);
    a.y = fmaf(h, w.y, a.y);
    a.z = fmaf(h, w.z, a.z);
    a.w = fmaf(h, w.w, a.w);
}

// Accumulate a K=512 GEMV slice for this thread's 4 columns (cg) and k-phase p,
// for two batch rows at once (h vectors live in shared memory).
__device__ __forceinline__ void gemv512(const float* __restrict__ W,
                                        const float* hrow0, const float* hrow1,
                                        int p, int cg, float4& a0, float4& a1) {
    const float* Wq = W + (size_t)(p * 128) * HH + 4 * cg;
    const float4* hh0 = (const float4*)(hrow0 + p * 128);
    const float4* hh1 = (const float4*)(hrow1 + p * 128);
#pragma unroll 4
    for (int m = 0; m < 32; ++m) {
        float4 h0v = hh0[m];
        float4 h1v = hh1[m];
        const float* wb = Wq + (size_t)(4 * m) * HH;
        float4 w0 = *(const float4*)(wb);
        float4 w1 = *(const float4*)(wb + HH);
        float4 w2 = *(const float4*)(wb + 2 * HH);
        float4 w3 = *(const float4*)(wb + 3 * HH);
        fma4(a0, h0v.x, w0); fma4(a1, h1v.x, w0);
        fma4(a0, h0v.y, w1); fma4(a1, h1v.y, w1);
        fma4(a0, h0v.z, w2); fma4(a1, h1v.z, w2);
        fma4(a0, h0v.w, w3); fma4(a1, h1v.w, w3);
    }
}

__global__ void __launch_bounds__(NTHR, 1)
rnn_forecaster_kernel(
    const float* __restrict__ x,
    const float* __restrict__ Wi0, const float* __restrict__ bi0,
    const float* __restrict__ Wh0, const float* __restrict__ bh0,
    const float* __restrict__ g0,  const float* __restrict__ be0,
    const float* __restrict__ Wi1, const float* __restrict__ bi1,
    const float* __restrict__ Wh1, const float* __restrict__ bh1,
    const float* __restrict__ g1,  const float* __restrict__ be1,
    const float* __restrict__ Wfc, const float* __restrict__ bfc,
    float* __restrict__ out)
{
    __shared__ float sh0[2][HH];          // layer-0 hidden state, 2 rows
    __shared__ float sh1[2][HH];          // layer-1 hidden state, 2 rows
    __shared__ float scb0[HH], scb1[HH];  // combined biases bi+bh
    __shared__ float sg0[HH], sbe0[HH], sg1[HH], sbe1[HH];
    __shared__ float sx[2][DIN];          // x_t for both rows
    __shared__ float red[4][128][8];      // k-phase partial sums
    __shared__ float wred[16][4];         // per-warp LN partials
    __shared__ float bc[2][2];            // (mu, rstd) per row

    const int tid  = threadIdx.x;
    const int cg   = tid & 127;   // column group: cols 4cg..4cg+3
    const int p    = tid >> 7;    // k-phase 0..3
    const int lane = tid & 31;
    const int wid  = tid >> 5;
    const int row0 = blockIdx.x * 2;
    const int j    = tid;         // column this thread owns post-reduction
    const int cg2  = j >> 2, cc = j & 3;

    for (int i = tid; i < HH; i += NTHR) {
        scb0[i] = bi0[i] + bh0[i];
        scb1[i] = bi1[i] + bh1[i];
        sg0[i] = g0[i];  sbe0[i] = be0[i];
        sg1[i] = g1[i];  sbe1[i] = be1[i];
        sh0[0][i] = 0.f; sh0[1][i] = 0.f;
        sh1[0][i] = 0.f; sh1[1][i] = 0.f;
    }
    __syncthreads();

    for (int t = 0; t < TSTEPS; ++t) {
        // stage x_t for both rows
        if (tid < 2 * DIN) {
            int r = tid >> 6, k = tid & 63;
            sx[r][k] = x[((size_t)(row0 + r) * TSTEPS + t) * DIN + k];
        }
        __syncthreads();

        // ================= layer 0 =================
        float4 a0 = make_float4(0.f, 0.f, 0.f, 0.f);
        float4 a1 = make_float4(0.f, 0.f, 0.f, 0.f);
        {
            // x_t @ Wi0 (K = 64 -> 16 k per phase)
            const float* Wp = Wi0 + (size_t)(p * 16) * HH + 4 * cg;
            const float4* hx0 = (const float4*)&sx[0][p * 16];
            const float4* hx1 = (const float4*)&sx[1][p * 16];
#pragma unroll
            for (int m = 0; m < 4; ++m) {
                float4 h0v = hx0[m];
                float4 h1v = hx1[m];
                const float* wb = Wp + (size_t)(4 * m) * HH;
                float4 w0 = *(const float4*)(wb);
                float4 w1 = *(const float4*)(wb + HH);
                float4 w2 = *(const float4*)(wb + 2 * HH);
                float4 w3 = *(const float4*)(wb + 3 * HH);
                fma4(a0, h0v.x, w0); fma4(a1, h1v.x, w0);
                fma4(a0, h0v.y, w1); fma4(a1, h1v.y, w1);
                fma4(a0, h0v.z, w2); fma4(a1, h1v.z, w2);
                fma4(a0, h0v.w, w3); fma4(a1, h1v.w, w3);
            }
            // h0 @ Wh0 (K = 512)
            gemv512(Wh0, &sh0[0][0], &sh0[1][0], p, cg, a0, a1);
        }
        *(float4*)&red[p][cg][0] = a0;
        *(float4*)&red[p][cg][4] = a1;
        __syncthreads();
        {
            float z0 = red[0][cg2][cc] + red[1][cg2][cc] + red[2][cg2][cc] + red[3][cg2][cc] + scb0[j];
            float z1 = red[0][cg2][4 + cc] + red[1][cg2][4 + cc] + red[2][cg2][4 + cc] + red[3][cg2][4 + cc] + scb0[j];
            float c0 = tanhf(z0) + sh0[0][j];
            float c1 = tanhf(z1) + sh0[1][j];
            float s0 = c0, s1 = c1, q0 = c0 * c0, q1 = c1 * c1;
#pragma unroll
            for (int o = 16; o; o >>= 1) {
                s0 += __shfl_xor_sync(0xffffffffu, s0, o);
                s1 += __shfl_xor_sync(0xffffffffu, s1, o);
                q0 += __shfl_xor_sync(0xffffffffu, q0, o);
                q1 += __shfl_xor_sync(0xffffffffu, q1, o);
            }
            if (lane == 0) { wred[wid][0] = s0; wred[wid][1] = s1; wred[wid][2] = q0; wred[wid][3] = q1; }
            __syncthreads();
            if (wid == 0) {
                float v0 = (lane < 16) ? wred[lane][0] : 0.f;
                float v1 = (lane < 16) ? wred[lane][1] : 0.f;
                float v2 = (lane < 16) ? wred[lane][2] : 0.f;
                float v3 = (lane < 16) ? wred[lane][3] : 0.f;
#pragma unroll
                for (int o = 8; o; o >>= 1) {
                    v0 += __shfl_xor_sync(0xffffffffu, v0, o);
                    v1 += __shfl_xor_sync(0xffffffffu, v1, o);
                    v2 += __shfl_xor_sync(0xffffffffu, v2, o);
                    v3 += __shfl_xor_sync(0xffffffffu, v3, o);
                }
                if (lane == 0) {
                    float mu0 = v0 * (1.f / HH), mu1 = v1 * (1.f / HH);
                    float var0 = v2 * (1.f / HH) - mu0 * mu0;
                    float var1 = v3 * (1.f / HH) - mu1 * mu1;
                    bc[0][0] = mu0; bc[0][1] = rsqrtf(var0 + EPSF);
                    bc[1][0] = mu1; bc[1][1] = rsqrtf(var1 + EPSF);
                }
            }
            __syncthreads();
            sh0[0][j] = (c0 - bc[0][0]) * bc[0][1] * sg0[j] + sbe0[j];
            sh0[1][j] = (c1 - bc[1][0]) * bc[1][1] * sg0[j] + sbe0[j];
        }
        __syncthreads();

        // ================= layer 1 =================
        a0 = make_float4(0.f, 0.f, 0.f, 0.f);
        a1 = make_float4(0.f, 0.f, 0.f, 0.f);
        gemv512(Wi1, &sh0[0][0], &sh0[1][0], p, cg, a0, a1);  // h0n @ Wi1
        gemv512(Wh1, &sh1[0][0], &sh1[1][0], p, cg, a0, a1);  // h1  @ Wh1
        *(float4*)&red[p][cg][0] = a0;
        *(float4*)&red[p][cg][4] = a1;
        __syncthreads();
        {
            float z0 = red[0][cg2][cc] + red[1][cg2][cc] + red[2][cg2][cc] + red[3][cg2][cc] + scb1[j];
            float z1 = red[0][cg2][4 + cc] + red[1][cg2][4 + cc] + red[2][cg2][4 + cc] + red[3][cg2][4 + cc] + scb1[j];
            float c0 = tanhf(z0) + sh1[0][j];
            float c1 = tanhf(z1) + sh1[1][j];
            float s0 = c0, s1 = c1, q0 = c0 * c0, q1 = c1 * c1;
#pragma unroll
            for (int o = 16; o; o >>= 1) {
                s0 += __shfl_xor_sync(0xffffffffu, s0, o);
                s1 += __shfl_xor_sync(0xffffffffu, s1, o);
                q0 += __shfl_xor_sync(0xffffffffu, q0, o);
                q1 += __shfl_xor_sync(0xffffffffu, q1, o);
            }
            if (lane == 0) { wred[wid][0] = s0; wred[wid][1] = s1; wred[wid][2] = q0; wred[wid][3] = q1; }
            __syncthreads();
            if (wid == 0) {
                float v0 = (lane < 16) ? wred[lane][0] : 0.f;
                float v1 = (lane < 16) ? wred[lane][1] : 0.f;
                float v2 = (lane < 16) ? wred[lane][2] : 0.f;
                float v3 = (lane < 16) ? wred[lane][3] : 0.f;
#pragma unroll
                for (int o = 8; o; o >>= 1) {
                    v0 += __shfl_xor_sync(0xffffffffu, v0, o);
                    v1 += __shfl_xor_sync(0xffffffffu, v1, o);
                    v2 += __shfl_xor_sync(0xffffffffu, v2, o);
                    v3 += __shfl_xor_sync(0xffffffffu, v3, o);
                }
                if (lane == 0) {
                    float mu0 = v0 * (1.f / HH), mu1 = v1 * (1.f / HH);
                    float var0 = v2 * (1.f / HH) - mu0 * mu0;
                    float var1 = v3 * (1.f / HH) - mu1 * mu1;
                    bc[0][0] = mu0; bc[0][1] = rsqrtf(var0 + EPSF);
                    bc[1][0] = mu1; bc[1][1] = rsqrtf(var1 + EPSF);
                }
            }
            __syncthreads();
            sh1[0][j] = (c0 - bc[0][0]) * bc[0][1] * sg1[j] + sbe1[j];
            sh1[1][j] = (c1 - bc[1][0]) * bc[1][1] * sg1[j] + sbe1[j];
        }
        __syncthreads();
    }

    // ======== output head: out[b] = h1[b] . Wfc + bfc ========
    {
        float v0 = sh1[0][j] * Wfc[j];
        float v1 = sh1[1][j] * Wfc[j];
#pragma unroll
        for (int o = 16; o; o >>= 1) {
            v0 += __shfl_xor_sync(0xffffffffu, v0, o);
            v1 += __shfl_xor_sync(0xffffffffu, v1, o);
        }
        if (lane == 0) { wred[wid][0] = v0; wred[wid][1] = v1; }
        __syncthreads();
        if (wid == 0) {
            float u0 = (lane < 16) ? wred[lane][0] : 0.f;
            float u1 = (lane < 16) ? wred[lane][1] : 0.f;
#pragma unroll
            for (int o = 8; o; o >>= 1) {
                u0 += __shfl_xor_sync(0xffffffffu, u0, o);
                u1 += __shfl_xor_sync(0xffffffffu, u1, o);
            }
            if (lane == 0) {
                float b = bfc[0];
                out[row0]     = u0 + b;
                out[row0 + 1] = u1 + b;
            }
        }
    }
}

extern "C" void kernel_launch(void* const* d_in, const int* in_sizes, int n_in,
                              void* d_out, int out_size) {
    (void)in_sizes; (void)n_in; (void)out_size;
    const float* x   = (const float*)d_in[0];
    const float* Wi0 = (const float*)d_in[1];
    const float* bi0 = (const float*)d_in[2];
    const float* Wh0 = (const float*)d_in[3];
    const float* bh0 = (const float*)d_in[4];
    const float* g0  = (const float*)d_in[5];
    const float* be0 = (const float*)d_in[6];
    const float* Wi1 = (const float*)d_in[7];
    const float* bi1 = (const float*)d_in[8];
    const float* Wh1 = (const float*)d_in[9];
    const float* bh1 = (const float*)d_in[10];
    const float* g1  = (const float*)d_in[11];
    const float* be1 = (const float*)d_in[12];
    const float* Wfc = (const float*)d_in[13];
    const float* bfc = (const float*)d_in[14];

    rnn_forecaster_kernel<<<BATCH / 2, NTHR>>>(
        x, Wi0, bi0, Wh0, bh0, g0, be0,
        Wi1, bi1, Wh1, bh1, g1, be1,
        Wfc, bfc, (float*)d_out);
}

// round 5
// speedup vs baseline: 1.0543x; 1.0543x over previous
#include <cuda_runtime.h>
#include <cstddef>

#define TSTEPS 1024
#define BATCH  128
#define DIN    64
#define HH     512
#define NTHR   512
#define EPSF   1e-5f

__device__ __forceinline__ void fma4(float4& a, float h, const float4 w) {
    a.x = fmaf(h, w.x, a.x);
    a.y = fmaf(h, w.y, a.y);
    a.z = fmaf(h, w.z, a.z);
    a.w = fmaf(h, w.w, a.w);
}

// Accumulate a K=512 GEMV slice for this thread's 4 columns (cg) and k-phase p,
// for two batch rows at once (h vectors live in shared memory).
__device__ __forceinline__ void gemv512(const float* __restrict__ W,
                                        const float* hrow0, const float* hrow1,
                                        int p, int cg, float4& a0, float4& a1) {
    const float* Wq = W + (size_t)(p * 128) * HH + 4 * cg;
    const float4* hh0 = (const float4*)(hrow0 + p * 128);
    const float4* hh1 = (const float4*)(hrow1 + p * 128);
#pragma unroll 4
    for (int m = 0; m < 32; ++m) {
        float4 h0v = hh0[m];
        float4 h1v = hh1[m];
        const float* wb = Wq + (size_t)(4 * m) * HH;
        float4 w0 = *(const float4*)(wb);
        float4 w1 = *(const float4*)(wb + HH);
        float4 w2 = *(const float4*)(wb + 2 * HH);
        float4 w3 = *(const float4*)(wb + 3 * HH);
        fma4(a0, h0v.x, w0); fma4(a1, h1v.x, w0);
        fma4(a0, h0v.y, w1); fma4(a1, h1v.y, w1);
        fma4(a0, h0v.z, w2); fma4(a1, h1v.z, w2);
        fma4(a0, h0v.w, w3); fma4(a1, h1v.w, w3);
    }
}

__global__ void __launch_bounds__(NTHR, 1)
rnn_forecaster_kernel(
    const float* __restrict__ x,
    const float* __restrict__ Wi0, const float* __restrict__ bi0,
    const float* __restrict__ Wh0, const float* __restrict__ bh0,
    const float* __restrict__ g0,  const float* __restrict__ be0,
    const float* __restrict__ Wi1, const float* __restrict__ bi1,
    const float* __restrict__ Wh1, const float* __restrict__ bh1,
    const float* __restrict__ g1,  const float* __restrict__ be1,
    const float* __restrict__ Wfc, const float* __restrict__ bfc,
    float* __restrict__ out)
{
    __shared__ float sh0[2][HH];          // layer-0 hidden state, 2 rows
    __shared__ float sh1[2][HH];          // layer-1 hidden state, 2 rows
    __shared__ float scb0[HH], scb1[HH];  // combined biases bi+bh
    __shared__ float sg0[HH], sbe0[HH], sg1[HH], sbe1[HH];
    __shared__ float sx[2][DIN];          // x_t for both rows
    __shared__ float red[4][128][8];      // k-phase partial sums
    __shared__ float wred[16][4];         // per-warp LN partials
    __shared__ float bc[2][2];            // (mu, rstd) per row

    const int tid  = threadIdx.x;
    const int cg   = tid & 127;   // column group: cols 4cg..4cg+3
    const int p    = tid >> 7;    // k-phase 0..3
    const int lane = tid & 31;
    const int wid  = tid >> 5;
    const int row0 = blockIdx.x * 2;
    const int j    = tid;         // column this thread owns post-reduction
    const int cg2  = j >> 2, cc = j & 3;

    for (int i = tid; i < HH; i += NTHR) {
        scb0[i] = bi0[i] + bh0[i];
        scb1[i] = bi1[i] + bh1[i];
        sg0[i] = g0[i];  sbe0[i] = be0[i];
        sg1[i] = g1[i];  sbe1[i] = be1[i];
        sh0[0][i] = 0.f; sh0[1][i] = 0.f;
        sh1[0][i] = 0.f; sh1[1][i] = 0.f;
    }
    __syncthreads();

    for (int t = 0; t < TSTEPS; ++t) {
        // stage x_t for both rows
        if (tid < 2 * DIN) {
            int r = tid >> 6, k = tid & 63;
            sx[r][k] = x[((size_t)(row0 + r) * TSTEPS + t) * DIN + k];
        }
        __syncthreads();

        // ================= layer 0 =================
        float4 a0 = make_float4(0.f, 0.f, 0.f, 0.f);
        float4 a1 = make_float4(0.f, 0.f, 0.f, 0.f);
        {
            // x_t @ Wi0 (K = 64 -> 16 k per phase)
            const float* Wp = Wi0 + (size_t)(p * 16) * HH + 4 * cg;
            const float4* hx0 = (const float4*)&sx[0][p * 16];
            const float4* hx1 = (const float4*)&sx[1][p * 16];
#pragma unroll
            for (int m = 0; m < 4; ++m) {
                float4 h0v = hx0[m];
                float4 h1v = hx1[m];
                const float* wb = Wp + (size_t)(4 * m) * HH;
                float4 w0 = *(const float4*)(wb);
                float4 w1 = *(const float4*)(wb + HH);
                float4 w2 = *(const float4*)(wb + 2 * HH);
                float4 w3 = *(const float4*)(wb + 3 * HH);
                fma4(a0, h0v.x, w0); fma4(a1, h1v.x, w0);
                fma4(a0, h0v.y, w1); fma4(a1, h1v.y, w1);
                fma4(a0, h0v.z, w2); fma4(a1, h1v.z, w2);
                fma4(a0, h0v.w, w3); fma4(a1, h1v.w, w3);
            }
            // h0 @ Wh0 (K = 512)
            gemv512(Wh0, &sh0[0][0], &sh0[1][0], p, cg, a0, a1);
        }
        *(float4*)&red[p][cg][0] = a0;
        *(float4*)&red[p][cg][4] = a1;
        __syncthreads();
        {
            float z0 = red[0][cg2][cc] + red[1][cg2][cc] + red[2][cg2][cc] + red[3][cg2][cc] + scb0[j];
            float z1 = red[0][cg2][4 + cc] + red[1][cg2][4 + cc] + red[2][cg2][4 + cc] + red[3][cg2][4 + cc] + scb0[j];
            float c0 = tanhf(z0) + sh0[0][j];
            float c1 = tanhf(z1) + sh0[1][j];
            float s0 = c0, s1 = c1, q0 = c0 * c0, q1 = c1 * c1;
#pragma unroll
            for (int o = 16; o; o >>= 1) {
                s0 += __shfl_xor_sync(0xffffffffu, s0, o);
                s1 += __shfl_xor_sync(0xffffffffu, s1, o);
                q0 += __shfl_xor_sync(0xffffffffu, q0, o);
                q1 += __shfl_xor_sync(0xffffffffu, q1, o);
            }
            if (lane == 0) { wred[wid][0] = s0; wred[wid][1] = s1; wred[wid][2] = q0; wred[wid][3] = q1; }
            __syncthreads();
            if (wid == 0) {
                float v0 = (lane < 16) ? wred[lane][0] : 0.f;
                float v1 = (lane < 16) ? wred[lane][1] : 0.f;
                float v2 = (lane < 16) ? wred[lane][2] : 0.f;
                float v3 = (lane < 16) ? wred[lane][3] : 0.f;
#pragma unroll
                for (int o = 8; o; o >>= 1) {
                    v0 += __shfl_xor_sync(0xffffffffu, v0, o);
                    v1 += __shfl_xor_sync(0xffffffffu, v1, o);
                    v2 += __shfl_xor_sync(0xffffffffu, v2, o);
                    v3 += __shfl_xor_sync(0xffffffffu, v3, o);
                }
                if (lane == 0) {
                    float mu0 = v0 * (1.f / HH), mu1 = v1 * (1.f / HH);
                    float var0 = v2 * (1.f / HH) - mu0 * mu0;
                    float var1 = v3 * (1.f / HH) - mu1 * mu1;
                    bc[0][0] = mu0; bc[0][1] = rsqrtf(var0 + EPSF);
                    bc[1][0] = mu1; bc[1][1] = rsqrtf(var1 + EPSF);
                }
            }
            __syncthreads();
            sh0[0][j] = (c0 - bc[0][0]) * bc[0][1] * sg0[j] + sbe0[j];
            sh0[1][j] = (c1 - bc[1][0]) * bc[1][1] * sg0[j] + sbe0[j];
        }
        __syncthreads();

        // ================= layer 1 =================
        a0 = make_float4(0.f, 0.f, 0.f, 0.f);
        a1 = make_float4(0.f, 0.f, 0.f, 0.f);
        gemv512(Wi1, &sh0[0][0], &sh0[1][0], p, cg, a0, a1);  // h0n @ Wi1
        gemv512(Wh1, &sh1[0][0], &sh1[1][0], p, cg, a0, a1);  // h1  @ Wh1
        *(float4*)&red[p][cg][0] = a0;
        *(float4*)&red[p][cg][4] = a1;
        __syncthreads();
        {
            float z0 = red[0][cg2][cc] + red[1][cg2][cc] + red[2][cg2][cc] + red[3][cg2][cc] + scb1[j];
            float z1 = red[0][cg2][4 + cc] + red[1][cg2][4 + cc] + red[2][cg2][4 + cc] + red[3][cg2][4 + cc] + scb1[j];
            float c0 = tanhf(z0) + sh1[0][j];
            float c1 = tanhf(z1) + sh1[1][j];
            float s0 = c0, s1 = c1, q0 = c0 * c0, q1 = c1 * c1;
#pragma unroll
            for (int o = 16; o; o >>= 1) {
                s0 += __shfl_xor_sync(0xffffffffu, s0, o);
                s1 += __shfl_xor_sync(0xffffffffu, s1, o);
                q0 += __shfl_xor_sync(0xffffffffu, q0, o);
                q1 += __shfl_xor_sync(0xffffffffu, q1, o);
            }
            if (lane == 0) { wred[wid][0] = s0; wred[wid][1] = s1; wred[wid][2] = q0; wred[wid][3] = q1; }
            __syncthreads();
            if (wid == 0) {
                float v0 = (lane < 16) ? wred[lane][0] : 0.f;
                float v1 = (lane < 16) ? wred[lane][1] : 0.f;
                float v2 = (lane < 16) ? wred[lane][2] : 0.f;
                float v3 = (lane < 16) ? wred[lane][3] : 0.f;
#pragma unroll
                for (int o = 8; o; o >>= 1) {
                    v0 += __shfl_xor_sync(0xffffffffu, v0, o);
                    v1 += __shfl_xor_sync(0xffffffffu, v1, o);
                    v2 += __shfl_xor_sync(0xffffffffu, v2, o);
                    v3 += __shfl_xor_sync(0xffffffffu, v3, o);
                }
                if (lane == 0) {
                    float mu0 = v0 * (1.f / HH), mu1 = v1 * (1.f / HH);
                    float var0 = v2 * (1.f / HH) - mu0 * mu0;
                    float var1 = v3 * (1.f / HH) - mu1 * mu1;
                    bc[0][0] = mu0; bc[0][1] = rsqrtf(var0 + EPSF);
                    bc[1][0] = mu1; bc[1][1] = rsqrtf(var1 + EPSF);
                }
            }
            __syncthreads();
            sh1[0][j] = (c0 - bc[0][0]) * bc[0][1] * sg1[j] + sbe1[j];
            sh1[1][j] = (c1 - bc[1][0]) * bc[1][1] * sg1[j] + sbe1[j];
        }
        __syncthreads();
    }

    // ======== output head: out[b] = h1[b] . Wfc + bfc ========
    {
        float v0 = sh1[0][j] * Wfc[j];
        float v1 = sh1[1][j] * Wfc[j];
#pragma unroll
        for (int o = 16; o; o >>= 1) {
            v0 += __shfl_xor_sync(0xffffffffu, v0, o);
            v1 += __shfl_xor_sync(0xffffffffu, v1, o);
        }
        if (lane == 0) { wred[wid][0] = v0; wred[wid][1] = v1; }
        __syncthreads();
        if (wid == 0) {
            float u0 = (lane < 16) ? wred[lane][0] : 0.f;
            float u1 = (lane < 16) ? wred[lane][1] : 0.f;
#pragma unroll
            for (int o = 8; o; o >>= 1) {
                u0 += __shfl_xor_sync(0xffffffffu, u0, o);
                u1 += __shfl_xor_sync(0xffffffffu, u1, o);
            }
            if (lane == 0) {
                float b = bfc[0];
                out[row0]     = u0 + b;
                out[row0 + 1] = u1 + b;
            }
        }
    }
}

extern "C" void kernel_launch(void* const* d_in, const int* in_sizes, int n_in,
                              void* d_out, int out_size) {
    (void)in_sizes; (void)n_in; (void)out_size;
    const float* x   = (const float*)d_in[0];
    const float* Wi0 = (const float*)d_in[1];
    const float* bi0 = (const float*)d_in[2];
    const float* Wh0 = (const float*)d_in[3];
    const float* bh0 = (const float*)d_in[4];
    const float* g0  = (const float*)d_in[5];
    const float* be0 = (const float*)d_in[6];
    const float* Wi1 = (const float*)d_in[7];
    const float* bi1 = (const float*)d_in[8];
    const float* Wh1 = (const float*)d_in[9];
    const float* bh1 = (const float*)d_in[10];
    const float* g1  = (const float*)d_in[11];
    const float* be1 = (const float*)d_in[12];
    const float* Wfc = (const float*)d_in[13];
    const float* bfc = (const float*)d_in[14];

    rnn_forecaster_kernel<<<BATCH / 2, NTHR>>>(
        x, Wi0, bi0, Wh0, bh0, g0, be0,
        Wi1, bi1, Wh1, bh1, g1, be1,
        Wfc, bfc, (float*)d_out);
}

// round 6
// speedup vs baseline: 1.0772x; 1.0217x over previous
#include <cuda_runtime.h>
#include <cstddef>

#define TSTEPS 1024
#define BATCH  128
#define DIN    64
#define HH     512
#define NG     8      // row groups
#define NC     16     // CTAs per group (col slices)
#define RG     16     // rows per group
#define CW     32     // cols per CTA slice
#define NTHR   512
#define PITCH  17     // float2 pitch per k-row (bank-conflict padding)
#define EPSF   1e-5f

typedef unsigned long long ull;

// Cross-CTA scratch (static device globals: allocation-free, zero-initialized).
__device__ float  g_C[2][NG][RG][HH];     // candidate c slices per stage
__device__ float2 g_P[2][NG][NC][RG];     // per-CTA LN partial (sum, sumsq)
__device__ int    g_cnt[NG];
__device__ volatile int g_sense[NG];

__device__ __forceinline__ ull ffma2(ull a, ull b, ull c) {
    ull d;
    asm("fma.rn.f32x2 %0, %1, %2, %3;" : "=l"(d) : "l"(a), "l"(b), "l"(c));
    return d;
}

// One k-step: 4 cols x 4 rows = 8 FFMA2. W: 16B global load (w pairs free),
// h: 4 dup-pairs from SMEM (LDS.64, broadcast across col-lanes).
__device__ __forceinline__ void kstep(const float* __restrict__ W,
                                      const float2* __restrict__ h, ull* acc) {
    ulonglong2 w = *reinterpret_cast<const ulonglong2*>(W);
    ull h0 = *reinterpret_cast<const ull*>(h);
    ull h1 = *reinterpret_cast<const ull*>(h + 1);
    ull h2 = *reinterpret_cast<const ull*>(h + 2);
    ull h3 = *reinterpret_cast<const ull*>(h + 3);
    acc[0] = ffma2(h0, w.x, acc[0]); acc[1] = ffma2(h0, w.y, acc[1]);
    acc[2] = ffma2(h1, w.x, acc[2]); acc[3] = ffma2(h1, w.y, acc[3]);
    acc[4] = ffma2(h2, w.x, acc[4]); acc[5] = ffma2(h2, w.y, acc[5]);
    acc[6] = ffma2(h3, w.x, acc[6]); acc[7] = ffma2(h3, w.y, acc[7]);
}

#define SMEM_FLOATS (19584 + 17408 + 9216 + 4*512 + 64 + 32)
#define SMEM_BYTES  (SMEM_FLOATS * 4)

__global__ void __launch_bounds__(NTHR, 1)
rnn_coop_kernel(
    const float* __restrict__ x,
    const float* __restrict__ Wi0, const float* __restrict__ bi0,
    const float* __restrict__ Wh0, const float* __restrict__ bh0,
    const float* __restrict__ g0,  const float* __restrict__ be0,
    const float* __restrict__ Wi1, const float* __restrict__ bi1,
    const float* __restrict__ Wh1, const float* __restrict__ bh1,
    const float* __restrict__ g1,  const float* __restrict__ be1,
    const float* __restrict__ Wfc, const float* __restrict__ bfc,
    float* __restrict__ out)
{
    extern __shared__ float sm[];
    float2* sh0   = (float2*)sm;                 // [576][PITCH]: k<64 = x_t (dup), 64..575 = h0 (dup)
    float2* sh1   = sh0 + 576 * PITCH;           // [512][PITCH]: h1 (dup)
    float*  red   = (float*)(sh1 + 512 * PITCH); // [16 phases][32 slots * 18]
    float*  sg0s  = red  + 9216;
    float*  sb0s  = sg0s + 512;
    float*  sg1s  = sb0s + 512;
    float*  sb1s  = sg1s + 512;
    float*  scb0s = sb1s + 512;                  // slice biases (bi+bh)
    float*  scb1s = scb0s + 32;
    float*  smu   = scb1s + 32;                  // per-row mu
    float*  srs   = smu + 16;                    // per-row rstd

    const int tid    = threadIdx.x;
    const int lane   = tid & 31;
    const int wid    = tid >> 5;        // GEMV: k-phase | epilogue: row
    const int cg     = lane >> 2;       // col group 0..7
    const int rq     = lane & 3;        // row quad 0..3
    const int cslice = blockIdx.x & (NC - 1);
    const int g      = blockIdx.x >> 4;
    const int c0     = cslice * CW;
    const int row0   = g * RG;
    const int colbase = c0 + 4 * cg;

    // ---- init ----
    sg0s[tid] = g0[tid];  sb0s[tid] = be0[tid];
    sg1s[tid] = g1[tid];  sb1s[tid] = be1[tid];
    if (tid < CW) {
        scb0s[tid] = bi0[c0 + tid] + bh0[c0 + tid];
        scb1s[tid] = bi1[c0 + tid] + bh1[c0 + tid];
    }
    for (int i = tid; i < 576 * PITCH; i += NTHR) sh0[i] = make_float2(0.f, 0.f);
    for (int i = tid; i < 512 * PITCH; i += NTHR) sh1[i] = make_float2(0.f, 0.f);
    __syncthreads();

    int bsense = 0;  // barrier local sense (tid 0 only)

    const int c = lane;          // epilogue: output col within slice
    const int r = wid;           // epilogue: output row
    const int slot = ((c >> 2) << 2) + (r >> 2);
    const int flat = ((r & 3) << 2) + (c & 3);
    const float* rrd = red + slot * 18 + flat;

    for (int t = 0; t < TSTEPS; ++t) {
        // ---- stage x_t (dup pairs) into sh0 rows 0..63 ----
        {
            int rA = tid >> 6, kA = tid & 63;
            float xv = x[((size_t)(row0 + rA) * TSTEPS + t) * DIN + kA];
            sh0[kA * PITCH + rA] = make_float2(xv, xv);
            int rB = rA + 8;
            float xv2 = x[((size_t)(row0 + rB) * TSTEPS + t) * DIN + kA];
            sh0[kA * PITCH + rB] = make_float2(xv2, xv2);
        }
        __syncthreads();

        // ================= stage 0: cand0 = tanh(xWi0 + h0Wh0 + b) =================
        {
            ull acc[8] = {0, 0, 0, 0, 0, 0, 0, 0};
            const int p = wid;
#pragma unroll
            for (int i = 0; i < 4; ++i) {           // k = p+16i in [0,64): x part
                int k = p + 16 * i;
                kstep(Wi0 + (size_t)k * HH + colbase, sh0 + k * PITCH + 4 * rq, acc);
            }
#pragma unroll 4
            for (int i = 4; i < 36; ++i) {          // k in [64,576): h0 part
                int k = p + 16 * i;
                kstep(Wh0 + (size_t)(k - 64) * HH + colbase, sh0 + k * PITCH + 4 * rq, acc);
            }
            float* rw = red + p * 576 + lane * 18;
#pragma unroll
            for (int q = 0; q < 8; ++q) *(ull*)(rw + 2 * q) = acc[q];
        }
        __syncthreads();
        {
            float z = 0.f;
#pragma unroll
            for (int p2 = 0; p2 < 16; ++p2) z += rrd[p2 * 576];
            z += scb0s[c];
            float hold = sh0[(64 + c0 + c) * PITCH + r].x;
            float cv = tanhf(z) + hold;
            float s = cv, q = cv * cv;
#pragma unroll
            for (int o = 16; o; o >>= 1) {
                s += __shfl_xor_sync(0xffffffffu, s, o);
                q += __shfl_xor_sync(0xffffffffu, q, o);
            }
            g_C[0][g][r][c0 + c] = cv;
            if (lane == 0) g_P[0][g][cslice][r] = make_float2(s, q);
        }
        __threadfence();
        __syncthreads();
        if (tid == 0) {
            bsense ^= 1;
            int a = atomicAdd(&g_cnt[g], 1);
            if (a == NC - 1) { g_cnt[g] = 0; __threadfence(); g_sense[g] = bsense; }
            else { while (g_sense[g] != bsense) {} __threadfence(); }
        }
        __syncthreads();
        {   // LN stats (per-row across 16 CTAs), redundantly in every CTA
            float2 pv = make_float2(0.f, 0.f);
            if (lane < NC) pv = __ldcg(&g_P[0][g][lane][wid]);
#pragma unroll
            for (int o = 8; o; o >>= 1) {
                pv.x += __shfl_xor_sync(0xffffffffu, pv.x, o);
                pv.y += __shfl_xor_sync(0xffffffffu, pv.y, o);
            }
            if (lane == 0) {
                float mu = pv.x * (1.f / HH);
                float var = pv.y * (1.f / HH) - mu * mu;
                smu[wid] = mu; srs[wid] = rsqrtf(var + EPSF);
            }
        }
        __syncthreads();
        {   // rebuild full h0n (dup) into sh0 rows 64..575
#pragma unroll 4
            for (int i = 0; i < RG; ++i) {
                float cvv = __ldcg(&g_C[0][g][i][tid]);
                float hv = (cvv - smu[i]) * srs[i] * sg0s[tid] + sb0s[tid];
                sh0[(64 + tid) * PITCH + i] = make_float2(hv, hv);
            }
        }
        __syncthreads();

        // ================= stage 1: cand1 = tanh(h0n Wi1 + h1 Wh1 + b) =================
        {
            ull acc[8] = {0, 0, 0, 0, 0, 0, 0, 0};
            const int p = wid;
#pragma unroll 4
            for (int i = 0; i < 32; ++i) {          // k = p+16i in [0,512): h0n
                int k = p + 16 * i;
                kstep(Wi1 + (size_t)k * HH + colbase, sh0 + (64 + k) * PITCH + 4 * rq, acc);
            }
#pragma unroll 4
            for (int i = 32; i < 64; ++i) {         // k in [512,1024): h1
                int k = p + 16 * i - 512;
                kstep(Wh1 + (size_t)k * HH + colbase, sh1 + k * PITCH + 4 * rq, acc);
            }
            float* rw = red + p * 576 + lane * 18;
#pragma unroll
            for (int q = 0; q < 8; ++q) *(ull*)(rw + 2 * q) = acc[q];
        }
        __syncthreads();
        {
            float z = 0.f;
#pragma unroll
            for (int p2 = 0; p2 < 16; ++p2) z += rrd[p2 * 576];
            z += scb1s[c];
            float hold = sh1[(c0 + c) * PITCH + r].x;
            float cv = tanhf(z) + hold;
            float s = cv, q = cv * cv;
#pragma unroll
            for (int o = 16; o; o >>= 1) {
                s += __shfl_xor_sync(0xffffffffu, s, o);
                q += __shfl_xor_sync(0xffffffffu, q, o);
            }
            g_C[1][g][r][c0 + c] = cv;
            if (lane == 0) g_P[1][g][cslice][r] = make_float2(s, q);
        }
        __threadfence();
        __syncthreads();
        if (tid == 0) {
            bsense ^= 1;
            int a = atomicAdd(&g_cnt[g], 1);
            if (a == NC - 1) { g_cnt[g] = 0; __threadfence(); g_sense[g] = bsense; }
            else { while (g_sense[g] != bsense) {} __threadfence(); }
        }
        __syncthreads();
        {
            float2 pv = make_float2(0.f, 0.f);
            if (lane < NC) pv = __ldcg(&g_P[1][g][lane][wid]);
#pragma unroll
            for (int o = 8; o; o >>= 1) {
                pv.x += __shfl_xor_sync(0xffffffffu, pv.x, o);
                pv.y += __shfl_xor_sync(0xffffffffu, pv.y, o);
            }
            if (lane == 0) {
                float mu = pv.x * (1.f / HH);
                float var = pv.y * (1.f / HH) - mu * mu;
                smu[wid] = mu; srs[wid] = rsqrtf(var + EPSF);
            }
        }
        __syncthreads();
        {
#pragma unroll 4
            for (int i = 0; i < RG; ++i) {
                float cvv = __ldcg(&g_C[1][g][i][tid]);
                float hv = (cvv - smu[i]) * srs[i] * sg1s[tid] + sb1s[tid];
                sh1[tid * PITCH + i] = make_float2(hv, hv);
            }
        }
        __syncthreads();
    }

    // ======== output head: out[b] = h1[b] . Wfc + bfc (slice-0 CTAs only) ========
    if (cslice == 0) {
        float v = 0.f;
#pragma unroll
        for (int m = 0; m < 16; ++m) {
            int k = lane + 32 * m;
            v += sh1[k * PITCH + wid].x * Wfc[k];
        }
#pragma unroll
        for (int o = 16; o; o >>= 1) v += __shfl_xor_sync(0xffffffffu, v, o);
        if (lane == 0) out[row0 + wid] = v + bfc[0];
    }
}

extern "C" void kernel_launch(void* const* d_in, const int* in_sizes, int n_in,
                              void* d_out, int out_size) {
    (void)in_sizes; (void)n_in; (void)out_size;
    const float* x   = (const float*)d_in[0];
    const float* Wi0 = (const float*)d_in[1];
    const float* bi0 = (const float*)d_in[2];
    const float* Wh0 = (const float*)d_in[3];
    const float* bh0 = (const float*)d_in[4];
    const float* g0  = (const float*)d_in[5];
    const float* be0 = (const float*)d_in[6];
    const float* Wi1 = (const float*)d_in[7];
    const float* bi1 = (const float*)d_in[8];
    const float* Wh1 = (const float*)d_in[9];
    const float* bh1 = (const float*)d_in[10];
    const float* g1  = (const float*)d_in[11];
    const float* be1 = (const float*)d_in[12];
    const float* Wfc = (const float*)d_in[13];
    const float* bfc = (const float*)d_in[14];

    cudaFuncSetAttribute(rnn_coop_kernel,
                         cudaFuncAttributeMaxDynamicSharedMemorySize, SMEM_BYTES);
    rnn_coop_kernel<<<NG * NC, NTHR, SMEM_BYTES>>>(
        x, Wi0, bi0, Wh0, bh0, g0, be0,
        Wi1, bi1, Wh1, bh1, g1, be1,
        Wfc, bfc, (float*)d_out);
}